// round 1
// baseline (speedup 1.0000x reference)
#include <cuda_runtime.h>
#include <mma.h>
#include <math.h>

using namespace nvcuda;

// Problem constants
constexpr int S_ = 1024;   // seq
constexpr int B_ = 32;     // batch
constexpr int E_ = 1024;   // embed dim
constexpr int P_ = 128;    // proj dim
constexpr int NQK = 2 * P_; // 256

// Scratch (device globals; no allocation allowed)
__device__ float g_qk[(size_t)B_ * S_ * NQK];   // [S*B, 256], row = s*B + b
__device__ float g_fwd[B_ * S_];
__device__ float g_bwd[B_ * S_];
__device__ float g_csp[B_ * S_];

// ---------------------------------------------------------------------------
// Stage 1: GEMM  qk[m][n] = sum_k ctx[m][k] * W[n][k]
// m = s*B + b (context is [S,B,E] so flat row order matches), N=256, K=1024.
// tf32 wmma m16n16k8, BM=64, BN=128, BK=32, 256 threads (8 warps, 2x4 layout,
// each warp computes a 32x32 tile = 2x2 fragments).
// ---------------------------------------------------------------------------
constexpr int GBM = 64;
constexpr int GBN = 128;
constexpr int GBK = 32;
constexpr int GLD = 36;   // padded leading dim (floats), 144B = mult of 16B

__global__ __launch_bounds__(256) void gemm_qk(const float* __restrict__ ctx,
                                               const float* __restrict__ W)
{
    __shared__ float As[GBM][GLD];
    __shared__ float Bs[GBN][GLD];

    const int m0 = blockIdx.y * GBM;
    const int n0 = blockIdx.x * GBN;
    const int tid = threadIdx.x;
    const int warp = tid >> 5;
    const int wr = warp & 1;   // 0..1  (row group of 32)
    const int wc = warp >> 1;  // 0..3  (col group of 32)

    wmma::fragment<wmma::accumulator, 16, 16, 8, float> acc[2][2];
#pragma unroll
    for (int i = 0; i < 2; i++)
#pragma unroll
        for (int j = 0; j < 2; j++)
            wmma::fill_fragment(acc[i][j], 0.0f);

    for (int k0 = 0; k0 < E_; k0 += GBK) {
        // Load A tile: 64 rows x 32 cols = 512 float4; 2 per thread
#pragma unroll
        for (int it = 0; it < 2; it++) {
            int idx = tid + it * 256;          // 0..511
            int r = idx >> 3;
            int c4 = (idx & 7) * 4;
            float4 v = *(const float4*)(ctx + (size_t)(m0 + r) * E_ + k0 + c4);
            *(float4*)&As[r][c4] = v;
        }
        // Load B tile: 128 rows x 32 cols = 1024 float4; 4 per thread
#pragma unroll
        for (int it = 0; it < 4; it++) {
            int idx = tid + it * 256;          // 0..1023
            int r = idx >> 3;
            int c4 = (idx & 7) * 4;
            float4 v = *(const float4*)(W + (size_t)(n0 + r) * E_ + k0 + c4);
            *(float4*)&Bs[r][c4] = v;
        }
        __syncthreads();

#pragma unroll
        for (int kk = 0; kk < GBK; kk += 8) {
            wmma::fragment<wmma::matrix_a, 16, 16, 8, wmma::precision::tf32,
                           wmma::row_major> afr[2];
            wmma::fragment<wmma::matrix_b, 16, 16, 8, wmma::precision::tf32,
                           wmma::col_major> bfr[2];
#pragma unroll
            for (int i = 0; i < 2; i++) {
                wmma::load_matrix_sync(afr[i], &As[wr * 32 + i * 16][kk], GLD);
#pragma unroll
                for (int t = 0; t < afr[i].num_elements; t++)
                    afr[i].x[t] = wmma::__float_to_tf32(afr[i].x[t]);
            }
#pragma unroll
            for (int j = 0; j < 2; j++) {
                wmma::load_matrix_sync(bfr[j], &Bs[wc * 32 + j * 16][kk], GLD);
#pragma unroll
                for (int t = 0; t < bfr[j].num_elements; t++)
                    bfr[j].x[t] = wmma::__float_to_tf32(bfr[j].x[t]);
            }
#pragma unroll
            for (int i = 0; i < 2; i++)
#pragma unroll
                for (int j = 0; j < 2; j++)
                    wmma::mma_sync(acc[i][j], afr[i], bfr[j], acc[i][j]);
        }
        __syncthreads();
    }

#pragma unroll
    for (int i = 0; i < 2; i++)
#pragma unroll
        for (int j = 0; j < 2; j++) {
            float* dst = g_qk + (size_t)(m0 + wr * 32 + i * 16) * NQK
                              + n0 + wc * 32 + j * 16;
            wmma::store_matrix_sync(dst, acc[i][j], NQK, wmma::mem_row_major);
        }
}

// ---------------------------------------------------------------------------
// Stage 2: fwd[b][s] = dot(Q[b,s], K[b,s+1]) / E,  bwd[b][s] = dot(Q[b,s+1], K[b,s]) / E
// (bias applied here; zero in this dataset but handled generally)
// grid (S-1, B), 128 threads (one per p)
// ---------------------------------------------------------------------------
__global__ __launch_bounds__(128) void scores(const float* __restrict__ bias)
{
    const int s = blockIdx.x;     // 0..S-2
    const int b = blockIdx.y;
    const int p = threadIdx.x;    // 0..127

    const float* row0 = g_qk + (size_t)(s * B_ + b) * NQK;
    const float* row1 = g_qk + (size_t)((s + 1) * B_ + b) * NQK;

    const float bq = bias[p];
    const float bk = bias[P_ + p];

    float q0 = row0[p] + bq;
    float k0 = row0[P_ + p] + bk;
    float q1 = row1[p] + bq;
    float k1 = row1[P_ + p] + bk;

    float tf = q0 * k1;
    float tb = q1 * k0;

    // reduce 128 -> 1 (two values)
    __shared__ float red[8];
    const unsigned lane = p & 31;
    const int w = p >> 5;
#pragma unroll
    for (int o = 16; o > 0; o >>= 1) {
        tf += __shfl_down_sync(0xffffffffu, tf, o);
        tb += __shfl_down_sync(0xffffffffu, tb, o);
    }
    if (lane == 0) { red[w] = tf; red[4 + w] = tb; }
    __syncthreads();
    if (p == 0) {
        float f = red[0] + red[1] + red[2] + red[3];
        float bb = red[4] + red[5] + red[6] + red[7];
        g_fwd[b * S_ + s] = f * (1.0f / (float)E_);
        g_bwd[b * S_ + s] = bb * (1.0f / (float)E_);
    }
}

// ---------------------------------------------------------------------------
// Stage 3: per-batch row ops + exclusive prefix scan.
// One block per batch, 1024 threads (one per s).
// ---------------------------------------------------------------------------
__global__ __launch_bounds__(1024) void rowscan(const float* __restrict__ prior,
                                                const int* __restrict__ mask,
                                                float* __restrict__ out_na)
{
    const int b = blockIdx.x;
    const int s = threadIdx.x;

    __shared__ float s_prob1[S_];
    __shared__ float s_warp[32];

    const int rm = mask[b * S_ + ((s + 1) & (S_ - 1))];  // rolled mask

    float c0 = (s < S_ - 1) ? g_fwd[b * S_ + s] : -INFINITY;
    if (rm == 1) c0 = -INFINITY;
    float c1 = (s > 0) ? g_bwd[b * S_ + s - 1] : -INFINITY;

    float mx = fmaxf(c0, c1);
    float e0 = __expf(c0 - mx);
    float e1 = __expf(c1 - mx);
    float inv = 1.0f / (e0 + e1);
    float p0 = e0 * inv;
    float p1 = e1 * inv;

    s_prob1[s] = p1;
    __syncthreads();

    float shift;
    if (s < S_ - 1) {
        shift = s_prob1[s + 1];
    } else {
        // flattened roll wraps into the next batch's position 0
        int b2 = (b + 1) % B_;
        float c0n = g_fwd[b2 * S_ + 0];
        if (mask[b2 * S_ + 1] == 1) c0n = -INFINITY;
        float mn = c0n;                   // max(c0n, -inf)
        float e0n = __expf(c0n - mn);
        float e1n = __expf(-INFINITY - mn);
        shift = e1n / (e0n + e1n);
    }

    float pv = sqrtf(p0 * shift + 1e-6f);
    float pr = prior[b * S_ + s];
    float na = pr + (1.0f - pr) * pv;
    out_na[b * S_ + s] = na;

    float lp = logf(na);
    if (rm == 1) lp = 0.0f;

    // block-wide inclusive scan of lp, then make exclusive
    float v = lp;
    const unsigned lane = s & 31;
#pragma unroll
    for (int o = 1; o < 32; o <<= 1) {
        float n = __shfl_up_sync(0xffffffffu, v, o);
        if (lane >= (unsigned)o) v += n;
    }
    if (lane == 31) s_warp[s >> 5] = v;
    __syncthreads();
    if (s < 32) {
        float w = s_warp[s];
#pragma unroll
        for (int o = 1; o < 32; o <<= 1) {
            float n = __shfl_up_sync(0xffffffffu, w, o);
            if (s >= o) w += n;
        }
        s_warp[s] = w;
    }
    __syncthreads();
    float incl = v + ((s >= 32) ? s_warp[(s >> 5) - 1] : 0.0f);
    float excl = incl - lp;           // sum_{k<s} lp[k]
    g_csp[b * S_ + s] = excl;
}

// ---------------------------------------------------------------------------
// Stage 4: constituent[b][i][j] = (i==j) ? 0 : exp(csp[max(i,j)] - csp[min(i,j)])
// grid (S, B), 256 threads, each thread writes one float4 (4 j's).
// ---------------------------------------------------------------------------
__global__ __launch_bounds__(256) void outerk(float* __restrict__ out)
{
    const int i = blockIdx.x;
    const int b = blockIdx.y;

    __shared__ float sc[S_];
    for (int t = threadIdx.x; t < S_; t += 256)
        sc[t] = g_csp[b * S_ + t];
    __syncthreads();

    const float ci = sc[i];
    const int j0 = threadIdx.x * 4;

    float4 r;
    float* rv = &r.x;
#pragma unroll
    for (int l = 0; l < 4; l++) {
        int j = j0 + l;
        float cj = sc[j];
        float d = (j > i) ? (cj - ci) : (ci - cj);
        rv[l] = (j == i) ? 0.0f : __expf(d);
    }
    *(float4*)(out + ((size_t)b * S_ + i) * S_ + j0) = r;
}

// ---------------------------------------------------------------------------
extern "C" void kernel_launch(void* const* d_in, const int* in_sizes, int n_in,
                              void* d_out, int out_size)
{
    const float* ctx   = (const float*)d_in[0];  // [S,B,E]
    const float* prior = (const float*)d_in[1];  // [B,S]
    const int*   mask  = (const int*)d_in[2];    // [B,S]
    const float* W     = (const float*)d_in[3];  // [2P,E]
    const float* bias  = (const float*)d_in[4];  // [2P]

    float* out_c  = (float*)d_out;                       // [B,S,S]
    float* out_na = (float*)d_out + (size_t)B_ * S_ * S_; // [B,S]

    dim3 g1(NQK / GBN, (B_ * S_) / GBM);   // (2, 512)
    gemm_qk<<<g1, 256>>>(ctx, W);

    dim3 g2(S_ - 1, B_);
    scores<<<g2, 128>>>(bias);

    rowscan<<<B_, S_>>>(prior, mask, out_na);

    dim3 g4(S_, B_);
    outerk<<<g4, 256>>>(out_c);
}

// round 2
// speedup vs baseline: 1.7664x; 1.7664x over previous
#include <cuda_runtime.h>
#include <cuda_bf16.h>
#include <mma.h>
#include <math.h>

using namespace nvcuda;

constexpr int S_ = 1024;
constexpr int B_ = 32;
constexpr int E_ = 1024;
constexpr int P_ = 128;
constexpr int NQK = 2 * P_;   // 256

__device__ float g_qk[(size_t)B_ * S_ * NQK];
__device__ float g_fwd[B_ * S_];
__device__ float g_bwd[B_ * S_];
__device__ float g_csp[B_ * S_];
__device__ float g_f[B_ * S_];

// ---------------------------------------------------------------------------
// Stage 1: GEMM  qk[m][n] = sum_k ctx[m][k] * W[n][k],  M=32768, N=256, K=1024
// bf16 wmma m16n16k16. BM=64, BN=256, BK=16. 256 threads (8 warps, 2x4),
// warp tile 32x64. Register-prefetch double buffering, 48B smem rows
// (conflict-free for ldmatrix-pattern loads).
// ---------------------------------------------------------------------------
constexpr int GBM = 64;
constexpr int GBK = 16;
constexpr int GLD = 24;   // bf16 elems per smem row = 48B (multiple of 16B)

__global__ __launch_bounds__(256, 2) void gemm_qk(const float* __restrict__ ctx,
                                                  const float* __restrict__ W)
{
    __shared__ __nv_bfloat16 As[2][GBM][GLD];
    __shared__ __nv_bfloat16 Bs[2][NQK][GLD];

    const int m0 = blockIdx.x * GBM;
    const int tid = threadIdx.x;
    const int warp = tid >> 5;
    const int wr = warp & 1;    // 0..1 (32-row group)
    const int wc = warp >> 1;   // 0..3 (64-col group)

    const int lr = tid >> 2;          // 0..63 (A row per thread)
    const int lc = (tid & 3) * 4;     // col start (float4)

    wmma::fragment<wmma::accumulator, 16, 16, 16, float> acc[2][4];
#pragma unroll
    for (int i = 0; i < 2; i++)
#pragma unroll
        for (int j = 0; j < 4; j++)
            wmma::fill_fragment(acc[i][j], 0.0f);

    float4 ra;        // A prefetch: 1 float4 / thread
    float4 rb[4];     // B prefetch: 4 float4 / thread

    auto ldg = [&](int k0) {
        ra = *(const float4*)(ctx + (size_t)(m0 + lr) * E_ + k0 + lc);
#pragma unroll
        for (int it = 0; it < 4; it++) {
            int r = (tid + it * 256) >> 2;
            rb[it] = *(const float4*)(W + (size_t)r * E_ + k0 + lc);
        }
    };
    auto sts = [&](int buf) {
        __nv_bfloat16* pa = &As[buf][lr][lc];
        pa[0] = __float2bfloat16(ra.x); pa[1] = __float2bfloat16(ra.y);
        pa[2] = __float2bfloat16(ra.z); pa[3] = __float2bfloat16(ra.w);
#pragma unroll
        for (int it = 0; it < 4; it++) {
            int r = (tid + it * 256) >> 2;
            __nv_bfloat16* pb = &Bs[buf][r][lc];
            pb[0] = __float2bfloat16(rb[it].x); pb[1] = __float2bfloat16(rb[it].y);
            pb[2] = __float2bfloat16(rb[it].z); pb[3] = __float2bfloat16(rb[it].w);
        }
    };

    ldg(0);
    sts(0);
    __syncthreads();

    constexpr int T = E_ / GBK;   // 64
    for (int t = 0; t < T; t++) {
        if (t + 1 < T) ldg((t + 1) * GBK);

        const int buf = t & 1;
        wmma::fragment<wmma::matrix_a, 16, 16, 16, __nv_bfloat16, wmma::row_major> af[2];
        wmma::fragment<wmma::matrix_b, 16, 16, 16, __nv_bfloat16, wmma::col_major> bf[4];
#pragma unroll
        for (int i = 0; i < 2; i++)
            wmma::load_matrix_sync(af[i], &As[buf][wr * 32 + i * 16][0], GLD);
#pragma unroll
        for (int j = 0; j < 4; j++)
            wmma::load_matrix_sync(bf[j], &Bs[buf][wc * 64 + j * 16][0], GLD);
#pragma unroll
        for (int i = 0; i < 2; i++)
#pragma unroll
            for (int j = 0; j < 4; j++)
                wmma::mma_sync(acc[i][j], af[i], bf[j], acc[i][j]);

        if (t + 1 < T) {
            sts((t + 1) & 1);
            __syncthreads();
        }
    }

#pragma unroll
    for (int i = 0; i < 2; i++)
#pragma unroll
        for (int j = 0; j < 4; j++) {
            float* dst = g_qk + (size_t)(m0 + wr * 32 + i * 16) * NQK
                              + wc * 64 + j * 16;
            wmma::store_matrix_sync(dst, acc[i][j], NQK, wmma::mem_row_major);
        }
}

// ---------------------------------------------------------------------------
// Stage 2: neighbor scores, one warp per (s,b) row pair. Coalesced float4.
// ---------------------------------------------------------------------------
__global__ __launch_bounds__(256) void scores(const float* __restrict__ bias)
{
    const int warp = threadIdx.x >> 5;
    const int lane = threadIdx.x & 31;
    const int m = blockIdx.x * 8 + warp;      // m = s*B + b
    const int s = m >> 5;
    const int b = m & 31;
    if (s >= S_ - 1) return;

    const float* r0 = g_qk + (size_t)m * NQK;
    const float* r1 = r0 + (size_t)B_ * NQK;  // (s+1, b)

    float4 q0 = *(const float4*)(r0 + lane * 4);
    float4 k0 = *(const float4*)(r0 + P_ + lane * 4);
    float4 q1 = *(const float4*)(r1 + lane * 4);
    float4 k1 = *(const float4*)(r1 + P_ + lane * 4);
    float4 bq = *(const float4*)(bias + lane * 4);
    float4 bk = *(const float4*)(bias + P_ + lane * 4);

    q0.x += bq.x; q0.y += bq.y; q0.z += bq.z; q0.w += bq.w;
    q1.x += bq.x; q1.y += bq.y; q1.z += bq.z; q1.w += bq.w;
    k0.x += bk.x; k0.y += bk.y; k0.z += bk.z; k0.w += bk.w;
    k1.x += bk.x; k1.y += bk.y; k1.z += bk.z; k1.w += bk.w;

    float tf = q0.x * k1.x + q0.y * k1.y + q0.z * k1.z + q0.w * k1.w;
    float tb = q1.x * k0.x + q1.y * k0.y + q1.z * k0.z + q1.w * k0.w;

#pragma unroll
    for (int o = 16; o > 0; o >>= 1) {
        tf += __shfl_down_sync(0xffffffffu, tf, o);
        tb += __shfl_down_sync(0xffffffffu, tb, o);
    }
    if (lane == 0) {
        g_fwd[b * S_ + s] = tf * (1.0f / (float)E_);
        g_bwd[b * S_ + s] = tb * (1.0f / (float)E_);
    }
}

// ---------------------------------------------------------------------------
// Stage 3: per-batch softmax/roll/log + exclusive prefix scan. Also stores
// f[s] = exp(log_prob[s]) (= neighbor_attn or 1 under mask) for stage 4.
// ---------------------------------------------------------------------------
__global__ __launch_bounds__(1024) void rowscan(const float* __restrict__ prior,
                                                const int* __restrict__ mask,
                                                float* __restrict__ out_na)
{
    const int b = blockIdx.x;
    const int s = threadIdx.x;

    __shared__ float s_prob1[S_];
    __shared__ float s_warp[32];

    const int rm = mask[b * S_ + ((s + 1) & (S_ - 1))];

    float c0 = (s < S_ - 1) ? g_fwd[b * S_ + s] : -INFINITY;
    if (rm == 1) c0 = -INFINITY;
    float c1 = (s > 0) ? g_bwd[b * S_ + s - 1] : -INFINITY;

    float mx = fmaxf(c0, c1);
    float e0 = __expf(c0 - mx);
    float e1 = __expf(c1 - mx);
    float inv = 1.0f / (e0 + e1);
    float p0 = e0 * inv;
    float p1 = e1 * inv;

    s_prob1[s] = p1;
    __syncthreads();

    float shift;
    if (s < S_ - 1) {
        shift = s_prob1[s + 1];
    } else {
        int b2 = (b + 1) % B_;
        float c0n = g_fwd[b2 * S_ + 0];
        if (mask[b2 * S_ + 1] == 1) c0n = -INFINITY;
        float e0n = __expf(c0n - c0n);
        shift = 0.0f / (e0n + 0.0f);   // exp(-inf)/... == 0
        shift = 0.0f;
        // replicate exactly: prob1 at (b2, s=0) is exp(-inf - max)/sum = 0
    }

    float pv = sqrtf(p0 * shift + 1e-6f);
    float pr = prior[b * S_ + s];
    float na = pr + (1.0f - pr) * pv;
    out_na[b * S_ + s] = na;

    float lp = logf(na);
    float fv = na;
    if (rm == 1) { lp = 0.0f; fv = 1.0f; }
    g_f[b * S_ + s] = fv;

    float v = lp;
    const unsigned lane = s & 31;
#pragma unroll
    for (int o = 1; o < 32; o <<= 1) {
        float n = __shfl_up_sync(0xffffffffu, v, o);
        if (lane >= (unsigned)o) v += n;
    }
    if (lane == 31) s_warp[s >> 5] = v;
    __syncthreads();
    if (s < 32) {
        float w = s_warp[s];
#pragma unroll
        for (int o = 1; o < 32; o <<= 1) {
            float n = __shfl_up_sync(0xffffffffu, w, o);
            if (s >= o) w += n;
        }
        s_warp[s] = w;
    }
    __syncthreads();
    float incl = v + ((s >= 32) ? s_warp[(s >> 5) - 1] : 0.0f);
    g_csp[b * S_ + s] = incl - lp;
}

// ---------------------------------------------------------------------------
// Stage 4: constituent[b][i][j]. Row-recurrence: within a thread's 8-elem run,
// one exp at the diagonal-side end, then multiply outward by f[] (<= ~1,
// graceful underflow, no division). Straddling threads use direct exps.
// ---------------------------------------------------------------------------
__global__ __launch_bounds__(128) void outerk(float* __restrict__ out)
{
    const int i = blockIdx.x;
    const int b = blockIdx.y;

    __shared__ float sc[S_];
    __shared__ float sf[S_];
    for (int t = threadIdx.x; t < S_; t += 128) {
        sc[t] = g_csp[b * S_ + t];
        sf[t] = g_f[b * S_ + t];
    }
    __syncthreads();

    const float ci = sc[i];
    const int j0 = threadIdx.x * 8;

    float r[8];
    if (j0 + 7 < i) {
        // entirely left of diagonal: out[i,j] = exp(csp[i]-csp[j]); recurse leftward
        float v = __expf(ci - sc[j0 + 7]);
        r[7] = v;
#pragma unroll
        for (int l = 6; l >= 0; l--) {
            v *= sf[j0 + l];
            r[l] = v;
        }
    } else if (j0 > i) {
        // entirely right: out[i,j] = exp(csp[j]-csp[i]); recurse rightward
        float v = __expf(sc[j0] - ci);
        r[0] = v;
#pragma unroll
        for (int l = 1; l < 8; l++) {
            v *= sf[j0 + l - 1];
            r[l] = v;
        }
    } else {
        // straddles diagonal: direct
#pragma unroll
        for (int l = 0; l < 8; l++) {
            int j = j0 + l;
            float d = (j > i) ? (sc[j] - ci) : (ci - sc[j]);
            r[l] = (j == i) ? 0.0f : __expf(d);
        }
    }

    float* dst = out + ((size_t)b * S_ + i) * S_ + j0;
    float4 v0 = make_float4(r[0], r[1], r[2], r[3]);
    float4 v1 = make_float4(r[4], r[5], r[6], r[7]);
    *(float4*)(dst)     = v0;
    *(float4*)(dst + 4) = v1;
}

// ---------------------------------------------------------------------------
extern "C" void kernel_launch(void* const* d_in, const int* in_sizes, int n_in,
                              void* d_out, int out_size)
{
    const float* ctx   = (const float*)d_in[0];
    const float* prior = (const float*)d_in[1];
    const int*   mask  = (const int*)d_in[2];
    const float* W     = (const float*)d_in[3];
    const float* bias  = (const float*)d_in[4];

    float* out_c  = (float*)d_out;
    float* out_na = (float*)d_out + (size_t)B_ * S_ * S_;

    gemm_qk<<<(B_ * S_) / GBM, 256>>>(ctx, W);

    scores<<<(B_ * S_) / 8, 256>>>(bias);

    rowscan<<<B_, S_>>>(prior, mask, out_na);

    dim3 g4(S_, B_);
    outerk<<<g4, 128>>>(out_c);
}

// round 4
// speedup vs baseline: 1.8643x; 1.0554x over previous
#include <cuda_runtime.h>
#include <cuda_bf16.h>
#include <mma.h>
#include <math.h>
#include <cstdint>

using namespace nvcuda;

constexpr int S_ = 1024;
constexpr int B_ = 32;
constexpr int E_ = 1024;
constexpr int P_ = 128;
constexpr int NQK = 2 * P_;   // 256

__device__ float g_qk[(size_t)B_ * S_ * NQK];
__device__ float g_fwd[B_ * S_];
__device__ float g_bwd[B_ * S_];
__device__ float g_csp[B_ * S_];
__device__ float g_f[B_ * S_];

// ---------------------------------------------------------------------------
// Stage 1: GEMM qk[m][n] = sum_k ctx[m][k]*W[n][k]. M=32768, N=256, K=1024.
// bf16 wmma m16n16k16. BM=128, BN=256, BK=16. 512 threads (16 warps 4x4),
// warp tile 32x64. Double-buffered smem, packed bf16x2 stores.
// ---------------------------------------------------------------------------
constexpr int GBM = 128;
constexpr int GBK = 16;
constexpr int GLD = 24;   // bf16 elems per smem row (48B, mult of 16B)

__global__ __launch_bounds__(512) void gemm_qk(const float* __restrict__ ctx,
                                               const float* __restrict__ W)
{
    __shared__ __nv_bfloat16 As[2][GBM][GLD];
    __shared__ __nv_bfloat16 Bs[2][NQK][GLD];

    const int m0 = blockIdx.x * GBM;
    const int tid = threadIdx.x;
    const int warp = tid >> 5;
    const int wr = warp & 3;    // 0..3 (32-row group)
    const int wc = warp >> 2;   // 0..3 (64-col group)

    const int lr = tid >> 2;          // 0..127 (A row)
    const int lc = (tid & 3) * 4;     // col start (float4)

    wmma::fragment<wmma::accumulator, 16, 16, 16, float> acc[2][4];
#pragma unroll
    for (int i = 0; i < 2; i++)
#pragma unroll
        for (int j = 0; j < 4; j++)
            wmma::fill_fragment(acc[i][j], 0.0f);

    float4 ra;
    float4 rb[2];

    auto ldg = [&](int k0) {
        ra = *(const float4*)(ctx + (size_t)(m0 + lr) * E_ + k0 + lc);
#pragma unroll
        for (int it = 0; it < 2; it++) {
            int r = (tid + it * 512) >> 2;   // 0..255
            rb[it] = *(const float4*)(W + (size_t)r * E_ + k0 + lc);
        }
    };
    auto sts = [&](int buf) {
        __nv_bfloat162 a01 = __floats2bfloat162_rn(ra.x, ra.y);
        __nv_bfloat162 a23 = __floats2bfloat162_rn(ra.z, ra.w);
        *(uint2*)&As[buf][lr][lc] =
            make_uint2(*(unsigned int*)&a01, *(unsigned int*)&a23);
#pragma unroll
        for (int it = 0; it < 2; it++) {
            int r = (tid + it * 512) >> 2;
            __nv_bfloat162 b01 = __floats2bfloat162_rn(rb[it].x, rb[it].y);
            __nv_bfloat162 b23 = __floats2bfloat162_rn(rb[it].z, rb[it].w);
            *(uint2*)&Bs[buf][r][lc] =
                make_uint2(*(unsigned int*)&b01, *(unsigned int*)&b23);
        }
    };

    ldg(0);
    sts(0);
    __syncthreads();

    constexpr int T = E_ / GBK;   // 64
    for (int t = 0; t < T; t++) {
        if (t + 1 < T) ldg((t + 1) * GBK);

        const int buf = t & 1;
        wmma::fragment<wmma::matrix_a, 16, 16, 16, __nv_bfloat16, wmma::row_major> af[2];
        wmma::fragment<wmma::matrix_b, 16, 16, 16, __nv_bfloat16, wmma::col_major> bf[4];
#pragma unroll
        for (int i = 0; i < 2; i++)
            wmma::load_matrix_sync(af[i], &As[buf][wr * 32 + i * 16][0], GLD);
#pragma unroll
        for (int j = 0; j < 4; j++)
            wmma::load_matrix_sync(bf[j], &Bs[buf][wc * 64 + j * 16][0], GLD);
#pragma unroll
        for (int i = 0; i < 2; i++)
#pragma unroll
            for (int j = 0; j < 4; j++)
                wmma::mma_sync(acc[i][j], af[i], bf[j], acc[i][j]);

        if (t + 1 < T) {
            sts((t + 1) & 1);
            __syncthreads();
        }
    }

#pragma unroll
    for (int i = 0; i < 2; i++)
#pragma unroll
        for (int j = 0; j < 4; j++) {
            float* dst = g_qk + (size_t)(m0 + wr * 32 + i * 16) * NQK
                              + wc * 64 + j * 16;
            wmma::store_matrix_sync(dst, acc[i][j], NQK, wmma::mem_row_major);
        }
}

// ---------------------------------------------------------------------------
// Stage 2: neighbor scores, one warp per (s,b). Coalesced float4.
// ---------------------------------------------------------------------------
__global__ __launch_bounds__(256) void scores(const float* __restrict__ bias)
{
    const int warp = threadIdx.x >> 5;
    const int lane = threadIdx.x & 31;
    const int m = blockIdx.x * 8 + warp;      // m = s*B + b
    const int s = m >> 5;
    const int b = m & 31;
    if (s >= S_ - 1) return;

    const float* r0 = g_qk + (size_t)m * NQK;
    const float* r1 = r0 + (size_t)B_ * NQK;

    float4 q0 = *(const float4*)(r0 + lane * 4);
    float4 k0 = *(const float4*)(r0 + P_ + lane * 4);
    float4 q1 = *(const float4*)(r1 + lane * 4);
    float4 k1 = *(const float4*)(r1 + P_ + lane * 4);
    float4 bq = *(const float4*)(bias + lane * 4);
    float4 bk = *(const float4*)(bias + P_ + lane * 4);

    q0.x += bq.x; q0.y += bq.y; q0.z += bq.z; q0.w += bq.w;
    q1.x += bq.x; q1.y += bq.y; q1.z += bq.z; q1.w += bq.w;
    k0.x += bk.x; k0.y += bk.y; k0.z += bk.z; k0.w += bk.w;
    k1.x += bk.x; k1.y += bk.y; k1.z += bk.z; k1.w += bk.w;

    float tf = q0.x * k1.x + q0.y * k1.y + q0.z * k1.z + q0.w * k1.w;
    float tb = q1.x * k0.x + q1.y * k0.y + q1.z * k0.z + q1.w * k0.w;

#pragma unroll
    for (int o = 16; o > 0; o >>= 1) {
        tf += __shfl_down_sync(0xffffffffu, tf, o);
        tb += __shfl_down_sync(0xffffffffu, tb, o);
    }
    if (lane == 0) {
        g_fwd[b * S_ + s] = tf * (1.0f / (float)E_);
        g_bwd[b * S_ + s] = tb * (1.0f / (float)E_);
    }
}

// ---------------------------------------------------------------------------
// Stage 3: softmax/roll/log + exclusive scan; stores f = exp(log_prob).
// ---------------------------------------------------------------------------
__global__ __launch_bounds__(1024) void rowscan(const float* __restrict__ prior,
                                                const int* __restrict__ mask,
                                                float* __restrict__ out_na)
{
    const int b = blockIdx.x;
    const int s = threadIdx.x;

    __shared__ float s_prob1[S_];
    __shared__ float s_warp[32];

    const int rm = mask[b * S_ + ((s + 1) & (S_ - 1))];

    float c0 = (s < S_ - 1) ? g_fwd[b * S_ + s] : -INFINITY;
    if (rm == 1) c0 = -INFINITY;
    float c1 = (s > 0) ? g_bwd[b * S_ + s - 1] : -INFINITY;

    float mx = fmaxf(c0, c1);
    float e0 = __expf(c0 - mx);
    float e1 = __expf(c1 - mx);
    float inv = 1.0f / (e0 + e1);
    float p0 = e0 * inv;
    float p1 = e1 * inv;

    s_prob1[s] = p1;
    __syncthreads();

    float shift;
    if (s < S_ - 1) {
        shift = s_prob1[s + 1];
    } else {
        shift = 0.0f;  // prob1 at (b+1, s=0): c1=-inf -> 0 regardless of mask
    }

    float pv = sqrtf(p0 * shift + 1e-6f);
    float pr = prior[b * S_ + s];
    float na = pr + (1.0f - pr) * pv;
    out_na[b * S_ + s] = na;

    float lp = logf(na);
    float fv = na;
    if (rm == 1) { lp = 0.0f; fv = 1.0f; }
    g_f[b * S_ + s] = fv;

    float v = lp;
    const unsigned lane = s & 31;
#pragma unroll
    for (int o = 1; o < 32; o <<= 1) {
        float n = __shfl_up_sync(0xffffffffu, v, o);
        if (lane >= (unsigned)o) v += n;
    }
    if (lane == 31) s_warp[s >> 5] = v;
    __syncthreads();
    if (s < 32) {
        float w = s_warp[s];
#pragma unroll
        for (int o = 1; o < 32; o <<= 1) {
            float n = __shfl_up_sync(0xffffffffu, w, o);
            if (s >= o) w += n;
        }
        s_warp[s] = w;
    }
    __syncthreads();
    float incl = v + ((s >= 32) ? s_warp[(s >> 5) - 1] : 0.0f);
    g_csp[b * S_ + s] = incl - lp;
}

// ---------------------------------------------------------------------------
// Stage 4: constituent[b][i][j]. 32 rows per block (256 threads), smem preload
// amortized. Per 8-elem chunk: 1 exp + 7 multiplies (recurrence with f <= ~1).
// ---------------------------------------------------------------------------
constexpr int RPB = 32;   // rows per block

__global__ __launch_bounds__(256) void outerk(float* __restrict__ out)
{
    const int b  = blockIdx.y;
    const int i0 = blockIdx.x * RPB;
    const int tid = threadIdx.x;

    __shared__ float sc[S_];
    __shared__ float sf[S_];
    {
        const float4* src_c = (const float4*)(g_csp + b * S_);
        const float4* src_f = (const float4*)(g_f + b * S_);
        ((float4*)sc)[tid] = src_c[tid];
        ((float4*)sf)[tid] = src_f[tid];
    }
    __syncthreads();

    const int rsub = tid >> 7;            // 0..1 (row within sweep pair)
    const int j0 = (tid & 127) * 8;

    float4 f0 = *(const float4*)&sf[j0];
    float4 f1 = *(const float4*)&sf[j0 + 4];
    float4 c0 = *(const float4*)&sc[j0];
    float4 c1 = *(const float4*)&sc[j0 + 4];

#pragma unroll 2
    for (int sweep = 0; sweep < RPB / 2; sweep++) {
        const int i = i0 + sweep * 2 + rsub;
        const float ci = sc[i];

        float r[8];
        if (j0 + 7 < i) {
            float v = __expf(ci - c1.w);          // exp(csp[i]-csp[j0+7])
            r[7] = v;
            v *= f1.z; r[6] = v;
            v *= f1.y; r[5] = v;
            v *= f1.x; r[4] = v;
            v *= f0.w; r[3] = v;
            v *= f0.z; r[2] = v;
            v *= f0.y; r[1] = v;
            v *= f0.x; r[0] = v;
        } else if (j0 > i) {
            float v = __expf(c0.x - ci);          // exp(csp[j0]-csp[i])
            r[0] = v;
            v *= f0.x; r[1] = v;
            v *= f0.y; r[2] = v;
            v *= f0.z; r[3] = v;
            v *= f0.w; r[4] = v;
            v *= f1.x; r[5] = v;
            v *= f1.y; r[6] = v;
            v *= f1.z; r[7] = v;
        } else {
            const float cj[8] = {c0.x, c0.y, c0.z, c0.w, c1.x, c1.y, c1.z, c1.w};
#pragma unroll
            for (int l = 0; l < 8; l++) {
                int j = j0 + l;
                float d = (j > i) ? (cj[l] - ci) : (ci - cj[l]);
                r[l] = (j == i) ? 0.0f : __expf(d);
            }
        }

        float* dst = out + ((size_t)b * S_ + i) * S_ + j0;
        *(float4*)(dst)     = make_float4(r[0], r[1], r[2], r[3]);
        *(float4*)(dst + 4) = make_float4(r[4], r[5], r[6], r[7]);
    }
}

// ---------------------------------------------------------------------------
extern "C" void kernel_launch(void* const* d_in, const int* in_sizes, int n_in,
                              void* d_out, int out_size)
{
    const float* ctx   = (const float*)d_in[0];
    const float* prior = (const float*)d_in[1];
    const int*   mask  = (const int*)d_in[2];
    const float* W     = (const float*)d_in[3];
    const float* bias  = (const float*)d_in[4];

    float* out_c  = (float*)d_out;
    float* out_na = (float*)d_out + (size_t)B_ * S_ * S_;

    gemm_qk<<<(B_ * S_) / GBM, 512>>>(ctx, W);

    scores<<<(B_ * S_) / 8, 256>>>(bias);

    rowscan<<<B_, S_>>>(prior, mask, out_na);

    dim3 g4(S_ / RPB, B_);
    outerk<<<g4, 256>>>(out_c);
}